// round 1
// baseline (speedup 1.0000x reference)
#include <cuda_runtime.h>
#include <cuda_bf16.h>
#include <cstdint>

// Problem constants (shapes fixed by the dataset)
#define N_MAX   50000
#define E_MAX   800000
#define G_CNT   512
#define FDIM    128
#define OUTD    200

// ---------------- device scratch (static, no allocation) ----------------
__device__ __align__(128) float g_x[N_MAX * FDIM];     // node features (ping)
__device__ __align__(128) float g_agg[N_MAX * FDIM];   // aggregated (pong)
__device__ __align__(128) float g_pool[G_CNT * FDIM];  // pooled per-graph
__device__ int   g_deg[2 * N_MAX];                     // [0..N) = deg_out, [N..2N) = deg_in
__device__ float g_norm_out[N_MAX];
__device__ float g_norm_in[N_MAX];
__device__ int   g_row_off[N_MAX + 1];
__device__ int   g_cursor[N_MAX];
__device__ int   g_esrc[E_MAX];                        // edge sources grouped by dst

// ---------------- kernels ----------------

__global__ void k_zero_deg(int n2) {
    for (int i = blockIdx.x * blockDim.x + threadIdx.x; i < n2; i += gridDim.x * blockDim.x)
        g_deg[i] = 0;
}

__global__ void k_deg(const int* __restrict__ src, const int* __restrict__ dst, int E, int n) {
    for (int e = blockIdx.x * blockDim.x + threadIdx.x; e < E; e += gridDim.x * blockDim.x) {
        atomicAdd(&g_deg[src[e]], 1);          // deg_out
        atomicAdd(&g_deg[n + dst[e]], 1);      // deg_in
    }
}

__global__ void k_norm(int n) {
    for (int i = blockIdx.x * blockDim.x + threadIdx.x; i < n; i += gridDim.x * blockDim.x) {
        g_norm_out[i] = rsqrtf(fmaxf((float)g_deg[i], 1.0f));
        g_norm_in[i]  = rsqrtf(fmaxf((float)g_deg[n + i], 1.0f));
    }
}

// Single-block exclusive scan of deg_in -> row_off, also zeroes cursor.
__global__ void k_scan(int n) {
    __shared__ int wsum[32];
    const int tid = threadIdx.x, lane = tid & 31, wid = tid >> 5;
    int carry = 0;
    if (tid == 0) g_row_off[0] = 0;
    for (int base = 0; base < n; base += 1024) {
        int i = base + tid;
        int v = (i < n) ? g_deg[n + i] : 0;   // deg_in
        if (i < n) g_cursor[i] = 0;
        int x = v;
        #pragma unroll
        for (int off = 1; off < 32; off <<= 1) {
            int t = __shfl_up_sync(0xffffffffu, x, off);
            if (lane >= off) x += t;
        }
        if (lane == 31) wsum[wid] = x;
        __syncthreads();
        if (wid == 0) {
            int w = wsum[lane];
            #pragma unroll
            for (int off = 1; off < 32; off <<= 1) {
                int t = __shfl_up_sync(0xffffffffu, w, off);
                if (lane >= off) w += t;
            }
            wsum[lane] = w;
        }
        __syncthreads();
        int incl = x + (wid > 0 ? wsum[wid - 1] : 0) + carry;
        if (i < n) g_row_off[i + 1] = incl;
        int tot = wsum[31];
        __syncthreads();
        carry += tot;
    }
}

__global__ void k_fill(const int* __restrict__ src, const int* __restrict__ dst, int E) {
    for (int e = blockIdx.x * blockDim.x + threadIdx.x; e < E; e += gridDim.x * blockDim.x) {
        int d = dst[e];
        int p = g_row_off[d] + atomicAdd(&g_cursor[d], 1);
        g_esrc[p] = src[e];
    }
}

// x = concat(init_embed[nid], z_table[z])  -- float4 granularity
__global__ void k_features(const int* __restrict__ nid, const int* __restrict__ z,
                           const float* __restrict__ init_embed,
                           const float* __restrict__ z_table, int n) {
    int total = n * 32;  // float4 units per node = 128/4
    for (int idx = blockIdx.x * blockDim.x + threadIdx.x; idx < total; idx += gridDim.x * blockDim.x) {
        int node = idx >> 5, q = idx & 31;
        float4 v;
        if (q < 16) v = __ldg(&((const float4*)init_embed)[(long)nid[node] * 16 + q]);
        else        v = __ldg(&((const float4*)z_table)[(long)z[node] * 16 + (q - 16)]);
        ((float4*)g_x)[node * 32 + q] = v;
    }
}

// SpMM gather-reduce: warp per dst node; lane covers 4 floats (float4).
// agg[d] = norm_in[d] * sum_{e in row(d)} norm_out[src] * x[src]
__global__ void __launch_bounds__(128) k_spmm(int n) {
    int warp = blockIdx.x * (blockDim.x >> 5) + (threadIdx.x >> 5);
    int lane = threadIdx.x & 31;
    if (warp >= n) return;
    int e0 = g_row_off[warp], e1 = g_row_off[warp + 1];
    float ax = 0.f, ay = 0.f, az = 0.f, aw = 0.f;
    const float4* x4 = (const float4*)g_x;
    for (int e = e0; e < e1; e++) {
        int s = __ldg(&g_esrc[e]);
        float w = __ldg(&g_norm_out[s]);
        float4 xv = __ldg(&x4[s * 32 + lane]);
        ax += w * xv.x; ay += w * xv.y; az += w * xv.z; aw += w * xv.w;
    }
    float ni = g_norm_in[warp];
    ((float4*)g_agg)[warp * 32 + lane] = make_float4(ax * ni, ay * ni, az * ni, aw * ni);
}

// Register-tiled SGEMM: out[n,128] = act(g_agg[n,128] @ W[128,128] + b)
// BM=128, BN=128, BK=16, 8x8 per thread, 256 threads/block.
__global__ void __launch_bounds__(256) k_gemm(const float* __restrict__ W,
                                              const float* __restrict__ bias,
                                              int n, int relu) {
    __shared__ float As[16][FDIM];  // [k][m]
    __shared__ float Bs[16][FDIM];  // [k][n]
    const int tid = threadIdx.x;
    const int tn = tid & 15;        // col group (8 cols)
    const int tm = tid >> 4;        // row group (8 rows)
    const int row0 = blockIdx.x * 128;

    float acc[8][8];
    #pragma unroll
    for (int i = 0; i < 8; i++)
        #pragma unroll
        for (int j = 0; j < 8; j++) acc[i][j] = 0.f;

    const float4* A4 = (const float4*)g_agg;
    const float4* W4 = (const float4*)W;

    for (int k0 = 0; k0 < FDIM; k0 += 16) {
        // A chunk: 128 rows x 16 k (512 float4), 2 float4/thread, stored transposed
        #pragma unroll
        for (int l = 0; l < 2; l++) {
            int fid = tid + l * 256;
            int r = fid >> 2;
            int kq = fid & 3;
            int grow = row0 + r;
            float4 v = make_float4(0.f, 0.f, 0.f, 0.f);
            if (grow < n) v = A4[grow * 32 + (k0 >> 2) + kq];
            As[kq * 4 + 0][r] = v.x;
            As[kq * 4 + 1][r] = v.y;
            As[kq * 4 + 2][r] = v.z;
            As[kq * 4 + 3][r] = v.w;
        }
        // W chunk: rows k0..k0+15 x 128 cols (512 float4)
        #pragma unroll
        for (int l = 0; l < 2; l++) {
            int fid = tid + l * 256;
            int kr = fid >> 5;
            int cq = fid & 31;
            float4 v = W4[(k0 + kr) * 32 + cq];
            *((float4*)&Bs[kr][cq * 4]) = v;
        }
        __syncthreads();
        #pragma unroll
        for (int kk = 0; kk < 16; kk++) {
            float4 a0 = *((const float4*)&As[kk][tm * 8]);
            float4 a1 = *((const float4*)&As[kk][tm * 8 + 4]);
            float4 b0 = *((const float4*)&Bs[kk][tn * 8]);
            float4 b1 = *((const float4*)&Bs[kk][tn * 8 + 4]);
            float a[8] = {a0.x, a0.y, a0.z, a0.w, a1.x, a1.y, a1.z, a1.w};
            float b[8] = {b0.x, b0.y, b0.z, b0.w, b1.x, b1.y, b1.z, b1.w};
            #pragma unroll
            for (int i = 0; i < 8; i++)
                #pragma unroll
                for (int j = 0; j < 8; j++)
                    acc[i][j] += a[i] * b[j];
        }
        __syncthreads();
    }

    // epilogue: bias + optional relu, write to g_x
    #pragma unroll
    for (int i = 0; i < 8; i++) {
        int grow = row0 + tm * 8 + i;
        if (grow >= n) break;
        float o[8];
        #pragma unroll
        for (int j = 0; j < 8; j++) {
            float v = acc[i][j] + __ldg(&bias[tn * 8 + j]);
            o[j] = relu ? fmaxf(v, 0.f) : v;
        }
        float4* dst4 = (float4*)&g_x[grow * FDIM + tn * 8];
        dst4[0] = make_float4(o[0], o[1], o[2], o[3]);
        dst4[1] = make_float4(o[4], o[5], o[6], o[7]);
    }
}

__global__ void k_zero_pool() {
    int i = blockIdx.x * blockDim.x + threadIdx.x;
    if (i < G_CNT * FDIM) g_pool[i] = 0.f;
}

__global__ void k_pool(const int* __restrict__ gid, int n) {
    int idx = blockIdx.x * blockDim.x + threadIdx.x;
    if (idx >= n * FDIM) return;
    int node = idx >> 7, c = idx & 127;
    atomicAdd(&g_pool[gid[node] * FDIM + c], g_x[idx]);
}

// Head: out[g] = relu(pool[g] @ lin1 + b1) @ lin2 + b2 ; block per graph
__global__ void __launch_bounds__(256) k_mlp(const float* __restrict__ lin1_W,
                                             const float* __restrict__ lin1_b,
                                             const float* __restrict__ lin2_W,
                                             const float* __restrict__ lin2_b,
                                             float* __restrict__ out) {
    __shared__ float gs[FDIM];
    __shared__ float hs[FDIM];
    const int g = blockIdx.x;
    const int tid = threadIdx.x;
    if (tid < FDIM) gs[tid] = g_pool[g * FDIM + tid];
    __syncthreads();
    if (tid < FDIM) {
        float acc = __ldg(&lin1_b[tid]);
        #pragma unroll 8
        for (int k = 0; k < FDIM; k++)
            acc += gs[k] * __ldg(&lin1_W[k * FDIM + tid]);
        hs[tid] = fmaxf(acc, 0.f);
    }
    __syncthreads();
    for (int c = tid; c < OUTD; c += blockDim.x) {
        float acc = __ldg(&lin2_b[c]);
        #pragma unroll 8
        for (int k = 0; k < FDIM; k++)
            acc += hs[k] * __ldg(&lin2_W[k * OUTD + c]);
        out[g * OUTD + c] = acc;
    }
}

// ---------------- launch ----------------
extern "C" void kernel_launch(void* const* d_in, const int* in_sizes, int n_in,
                              void* d_out, int out_size) {
    const int*   nid        = (const int*)  d_in[0];
    const int*   z          = (const int*)  d_in[1];
    const int*   src        = (const int*)  d_in[2];
    const int*   dst        = (const int*)  d_in[3];
    const int*   graph_id   = (const int*)  d_in[4];
    const float* init_embed = (const float*)d_in[5];
    const float* z_table    = (const float*)d_in[6];
    const float* W0 = (const float*)d_in[7];
    const float* b0 = (const float*)d_in[8];
    const float* W1 = (const float*)d_in[9];
    const float* b1 = (const float*)d_in[10];
    const float* W2 = (const float*)d_in[11];
    const float* b2 = (const float*)d_in[12];
    const float* lin1_W = (const float*)d_in[13];
    const float* lin1_b = (const float*)d_in[14];
    const float* lin2_W = (const float*)d_in[15];
    const float* lin2_b = (const float*)d_in[16];
    float* out = (float*)d_out;

    const int n = in_sizes[0];       // 50000
    const int E = in_sizes[2];       // 800000

    // 1) degrees
    k_zero_deg<<<256, 256>>>(2 * n);
    k_deg<<<(E + 511) / 512, 512>>>(src, dst, E, n);
    k_norm<<<(n + 255) / 256, 256>>>(n);

    // 2) CSR by dst
    k_scan<<<1, 1024>>>(n);
    k_fill<<<(E + 511) / 512, 512>>>(src, dst, E);

    // 3) node features
    k_features<<<(n * 32 + 255) / 256, 256>>>(nid, z, init_embed, z_table, n);

    // 4) 3 GCN layers (spmm: x->agg, gemm: agg->x)
    const int spmm_blocks = (n + 3) / 4;
    const int gemm_blocks = (n + 127) / 128;
    k_spmm<<<spmm_blocks, 128>>>(n);
    k_gemm<<<gemm_blocks, 256>>>(W0, b0, n, 1);
    k_spmm<<<spmm_blocks, 128>>>(n);
    k_gemm<<<gemm_blocks, 256>>>(W1, b1, n, 1);
    k_spmm<<<spmm_blocks, 128>>>(n);
    k_gemm<<<gemm_blocks, 256>>>(W2, b2, n, 0);

    // 5) sum pooling
    k_zero_pool<<<(G_CNT * FDIM + 255) / 256, 256>>>();
    k_pool<<<(n * FDIM + 255) / 256, 256>>>(graph_id, n);

    // 6) MLP head
    k_mlp<<<G_CNT, 256>>>(lin1_W, lin1_b, lin2_W, lin2_b, out);
}

// round 2
// speedup vs baseline: 1.1306x; 1.1306x over previous
#include <cuda_runtime.h>
#include <cuda_bf16.h>
#include <cstdint>

// Problem constants (shapes fixed by the dataset)
#define N_MAX   50000
#define E_MAX   800000
#define G_CNT   512
#define FDIM    128
#define OUTD    200
#define SCAN_B  1024

// ---------------- device scratch (static, no allocation) ----------------
__device__ __align__(128) float g_x[N_MAX * FDIM];     // node features (ping)
__device__ __align__(128) float g_agg[N_MAX * FDIM];   // aggregated (pong)
__device__ int   g_deg[2 * N_MAX];                     // [0..N) = deg_out, [N..2N) = deg_in
__device__ float g_norm_out[N_MAX];
__device__ float g_norm_in[N_MAX];
__device__ int   g_row_off[N_MAX + 1];
__device__ int   g_cursor[N_MAX];
__device__ int   g_esrc[E_MAX];                        // edge sources grouped by dst
__device__ int   g_bsum[64];                           // block sums for the scan

// ---------------- kernels ----------------

__global__ void k_zero_deg(int n2) {
    for (int i = blockIdx.x * blockDim.x + threadIdx.x; i < n2; i += gridDim.x * blockDim.x)
        g_deg[i] = 0;
}

__global__ void k_deg(const int* __restrict__ src, const int* __restrict__ dst, int E, int n) {
    for (int e = blockIdx.x * blockDim.x + threadIdx.x; e < E; e += gridDim.x * blockDim.x) {
        atomicAdd(&g_deg[src[e]], 1);          // deg_out
        atomicAdd(&g_deg[n + dst[e]], 1);      // deg_in
    }
}

// Phase 1: per-block inclusive scan of deg_in -> g_row_off[i+1] (block-local),
// block total -> g_bsum. Also fuses norm computation and cursor zeroing.
__global__ void __launch_bounds__(SCAN_B) k_scan1(int n) {
    __shared__ int wsum[32];
    const int tid = threadIdx.x, lane = tid & 31, wid = tid >> 5;
    const int i = blockIdx.x * SCAN_B + tid;
    int v = 0;
    if (i < n) {
        v = g_deg[n + i];                       // deg_in
        g_cursor[i] = 0;
        g_norm_out[i] = rsqrtf(fmaxf((float)g_deg[i], 1.0f));
        g_norm_in[i]  = rsqrtf(fmaxf((float)v, 1.0f));
    }
    int x = v;
    #pragma unroll
    for (int off = 1; off < 32; off <<= 1) {
        int t = __shfl_up_sync(0xffffffffu, x, off);
        if (lane >= off) x += t;
    }
    if (lane == 31) wsum[wid] = x;
    __syncthreads();
    if (wid == 0) {
        int w = wsum[lane];
        #pragma unroll
        for (int off = 1; off < 32; off <<= 1) {
            int t = __shfl_up_sync(0xffffffffu, w, off);
            if (lane >= off) w += t;
        }
        wsum[lane] = w;
    }
    __syncthreads();
    int incl = x + (wid > 0 ? wsum[wid - 1] : 0);
    if (i < n) g_row_off[i + 1] = incl;
    if (tid == SCAN_B - 1) g_bsum[blockIdx.x] = incl;   // block total
    if (i == 0) g_row_off[0] = 0;
}

// Phase 2: exclusive scan of <=64 block sums in a single warp.
__global__ void k_scan2(int nb) {
    const int lane = threadIdx.x;   // 32 threads
    int v0 = (lane < nb) ? g_bsum[lane] : 0;
    int v1 = (lane + 32 < nb) ? g_bsum[lane + 32] : 0;
    int x0 = v0, x1 = v1;
    #pragma unroll
    for (int off = 1; off < 32; off <<= 1) {
        int t0 = __shfl_up_sync(0xffffffffu, x0, off);
        int t1 = __shfl_up_sync(0xffffffffu, x1, off);
        if (lane >= off) { x0 += t0; x1 += t1; }
    }
    int tot0 = __shfl_sync(0xffffffffu, x0, 31);
    // exclusive = inclusive - self
    if (lane < nb) g_bsum[lane] = x0 - v0;
    if (lane + 32 < nb) g_bsum[lane + 32] = x1 - v1 + tot0;
}

// Phase 3: add block offsets.
__global__ void __launch_bounds__(SCAN_B) k_scan3(int n) {
    int i = blockIdx.x * SCAN_B + threadIdx.x;
    if (i < n) g_row_off[i + 1] += g_bsum[blockIdx.x];
}

__global__ void k_fill(const int* __restrict__ src, const int* __restrict__ dst, int E) {
    for (int e = blockIdx.x * blockDim.x + threadIdx.x; e < E; e += gridDim.x * blockDim.x) {
        int d = dst[e];
        int p = g_row_off[d] + atomicAdd(&g_cursor[d], 1);
        g_esrc[p] = src[e];
    }
}

// x = concat(init_embed[nid], z_table[z])  -- float4 granularity
__global__ void k_features(const int* __restrict__ nid, const int* __restrict__ z,
                           const float* __restrict__ init_embed,
                           const float* __restrict__ z_table, int n) {
    int total = n * 32;  // float4 units per node = 128/4
    for (int idx = blockIdx.x * blockDim.x + threadIdx.x; idx < total; idx += gridDim.x * blockDim.x) {
        int node = idx >> 5, q = idx & 31;
        float4 v;
        if (q < 16) v = __ldg(&((const float4*)init_embed)[(long)nid[node] * 16 + q]);
        else        v = __ldg(&((const float4*)z_table)[(long)z[node] * 16 + (q - 16)]);
        ((float4*)g_x)[node * 32 + q] = v;
    }
}

// SpMM gather-reduce: warp per dst node; lane covers 4 floats (float4).
// agg[d] = norm_in[d] * sum_{e in row(d)} norm_out[src] * x[src]
// Edge loop unrolled x2 for memory-level parallelism.
__global__ void __launch_bounds__(128) k_spmm(int n) {
    int warp = blockIdx.x * (blockDim.x >> 5) + (threadIdx.x >> 5);
    int lane = threadIdx.x & 31;
    if (warp >= n) return;
    int e0 = g_row_off[warp], e1 = g_row_off[warp + 1];
    float ax = 0.f, ay = 0.f, az = 0.f, aw = 0.f;
    float bx = 0.f, by = 0.f, bz = 0.f, bw = 0.f;
    const float4* x4 = (const float4*)g_x;
    int e = e0;
    for (; e + 1 < e1; e += 2) {
        int s0 = __ldg(&g_esrc[e]);
        int s1 = __ldg(&g_esrc[e + 1]);
        float w0 = __ldg(&g_norm_out[s0]);
        float w1 = __ldg(&g_norm_out[s1]);
        float4 v0 = __ldg(&x4[s0 * 32 + lane]);
        float4 v1 = __ldg(&x4[s1 * 32 + lane]);
        ax += w0 * v0.x; ay += w0 * v0.y; az += w0 * v0.z; aw += w0 * v0.w;
        bx += w1 * v1.x; by += w1 * v1.y; bz += w1 * v1.z; bw += w1 * v1.w;
    }
    if (e < e1) {
        int s0 = __ldg(&g_esrc[e]);
        float w0 = __ldg(&g_norm_out[s0]);
        float4 v0 = __ldg(&x4[s0 * 32 + lane]);
        ax += w0 * v0.x; ay += w0 * v0.y; az += w0 * v0.z; aw += w0 * v0.w;
    }
    float ni = g_norm_in[warp];
    ((float4*)g_agg)[warp * 32 + lane] =
        make_float4((ax + bx) * ni, (ay + by) * ni, (az + bz) * ni, (aw + bw) * ni);
}

// Register-tiled SGEMM: out[n,128] = act(g_agg[n,128] @ W[128,128] + b)
// BM=128, BN=128, BK=16, 8x8 per thread, 256 threads/block.
__global__ void __launch_bounds__(256) k_gemm(const float* __restrict__ W,
                                              const float* __restrict__ bias,
                                              int n, int relu) {
    __shared__ float As[16][FDIM];  // [k][m]
    __shared__ float Bs[16][FDIM];  // [k][n]
    const int tid = threadIdx.x;
    const int tn = tid & 15;        // col group (8 cols)
    const int tm = tid >> 4;        // row group (8 rows)
    const int row0 = blockIdx.x * 128;

    float acc[8][8];
    #pragma unroll
    for (int i = 0; i < 8; i++)
        #pragma unroll
        for (int j = 0; j < 8; j++) acc[i][j] = 0.f;

    const float4* A4 = (const float4*)g_agg;
    const float4* W4 = (const float4*)W;

    for (int k0 = 0; k0 < FDIM; k0 += 16) {
        #pragma unroll
        for (int l = 0; l < 2; l++) {
            int fid = tid + l * 256;
            int r = fid >> 2;
            int kq = fid & 3;
            int grow = row0 + r;
            float4 v = make_float4(0.f, 0.f, 0.f, 0.f);
            if (grow < n) v = A4[grow * 32 + (k0 >> 2) + kq];
            As[kq * 4 + 0][r] = v.x;
            As[kq * 4 + 1][r] = v.y;
            As[kq * 4 + 2][r] = v.z;
            As[kq * 4 + 3][r] = v.w;
        }
        #pragma unroll
        for (int l = 0; l < 2; l++) {
            int fid = tid + l * 256;
            int kr = fid >> 5;
            int cq = fid & 31;
            float4 v = W4[(k0 + kr) * 32 + cq];
            *((float4*)&Bs[kr][cq * 4]) = v;
        }
        __syncthreads();
        #pragma unroll
        for (int kk = 0; kk < 16; kk++) {
            float4 a0 = *((const float4*)&As[kk][tm * 8]);
            float4 a1 = *((const float4*)&As[kk][tm * 8 + 4]);
            float4 b0 = *((const float4*)&Bs[kk][tn * 8]);
            float4 b1 = *((const float4*)&Bs[kk][tn * 8 + 4]);
            float a[8] = {a0.x, a0.y, a0.z, a0.w, a1.x, a1.y, a1.z, a1.w};
            float b[8] = {b0.x, b0.y, b0.z, b0.w, b1.x, b1.y, b1.z, b1.w};
            #pragma unroll
            for (int i = 0; i < 8; i++)
                #pragma unroll
                for (int j = 0; j < 8; j++)
                    acc[i][j] += a[i] * b[j];
        }
        __syncthreads();
    }

    #pragma unroll
    for (int i = 0; i < 8; i++) {
        int grow = row0 + tm * 8 + i;
        if (grow >= n) break;
        float o[8];
        #pragma unroll
        for (int j = 0; j < 8; j++) {
            float v = acc[i][j] + __ldg(&bias[tn * 8 + j]);
            o[j] = relu ? fmaxf(v, 0.f) : v;
        }
        float4* dst4 = (float4*)&g_x[grow * FDIM + tn * 8];
        dst4[0] = make_float4(o[0], o[1], o[2], o[3]);
        dst4[1] = make_float4(o[4], o[5], o[6], o[7]);
    }
}

// Fused pooling + MLP head. graph_id is sorted, so each graph's nodes are a
// contiguous range: binary search bounds, segmented column-sum (coalesced),
// then the 2-layer head. Block per graph, 256 threads.
__global__ void __launch_bounds__(256) k_pool_mlp(const int* __restrict__ gid, int n,
                                                  const float* __restrict__ lin1_W,
                                                  const float* __restrict__ lin1_b,
                                                  const float* __restrict__ lin2_W,
                                                  const float* __restrict__ lin2_b,
                                                  float* __restrict__ out) {
    __shared__ float gs[FDIM];
    __shared__ float hs[FDIM];
    __shared__ int s_lo, s_hi;
    const int g = blockIdx.x;
    const int tid = threadIdx.x;

    if (tid == 0) {
        int lo = 0, hi = n;
        while (lo < hi) { int m = (lo + hi) >> 1; if (__ldg(&gid[m]) < g) lo = m + 1; else hi = m; }
        s_lo = lo;
    } else if (tid == 32) {
        int lo = 0, hi = n;
        while (lo < hi) { int m = (lo + hi) >> 1; if (__ldg(&gid[m]) <= g) lo = m + 1; else hi = m; }
        s_hi = lo;
    }
    __syncthreads();

    // segmented sum over contiguous node range; two columns per thread
    const int lo = s_lo, hi = s_hi;
    {
        int c0 = tid, c1 = tid + 128;  // wait: only 128 cols; use 128 threads w/ 1 col
    }
    if (tid < FDIM) {
        float acc = 0.f;
        for (int node = lo; node < hi; node++)
            acc += g_x[node * FDIM + tid];
        gs[tid] = acc;
    }
    __syncthreads();
    if (tid < FDIM) {
        float acc = __ldg(&lin1_b[tid]);
        #pragma unroll 8
        for (int k = 0; k < FDIM; k++)
            acc += gs[k] * __ldg(&lin1_W[k * FDIM + tid]);
        hs[tid] = fmaxf(acc, 0.f);
    }
    __syncthreads();
    for (int c = tid; c < OUTD; c += blockDim.x) {
        float acc = __ldg(&lin2_b[c]);
        #pragma unroll 8
        for (int k = 0; k < FDIM; k++)
            acc += hs[k] * __ldg(&lin2_W[k * OUTD + c]);
        out[g * OUTD + c] = acc;
    }
}

// ---------------- launch ----------------
extern "C" void kernel_launch(void* const* d_in, const int* in_sizes, int n_in,
                              void* d_out, int out_size) {
    const int*   nid        = (const int*)  d_in[0];
    const int*   z          = (const int*)  d_in[1];
    const int*   src        = (const int*)  d_in[2];
    const int*   dst        = (const int*)  d_in[3];
    const int*   graph_id   = (const int*)  d_in[4];
    const float* init_embed = (const float*)d_in[5];
    const float* z_table    = (const float*)d_in[6];
    const float* W0 = (const float*)d_in[7];
    const float* b0 = (const float*)d_in[8];
    const float* W1 = (const float*)d_in[9];
    const float* b1 = (const float*)d_in[10];
    const float* W2 = (const float*)d_in[11];
    const float* b2 = (const float*)d_in[12];
    const float* lin1_W = (const float*)d_in[13];
    const float* lin1_b = (const float*)d_in[14];
    const float* lin2_W = (const float*)d_in[15];
    const float* lin2_b = (const float*)d_in[16];
    float* out = (float*)d_out;

    const int n = in_sizes[0];       // 50000
    const int E = in_sizes[2];       // 800000
    const int nb = (n + SCAN_B - 1) / SCAN_B;

    // 1) degrees
    k_zero_deg<<<256, 256>>>(2 * n);
    k_deg<<<(E + 511) / 512, 512>>>(src, dst, E, n);

    // 2) norms + CSR row offsets (3-phase scan), then fill
    k_scan1<<<nb, SCAN_B>>>(n);
    k_scan2<<<1, 32>>>(nb);
    k_scan3<<<nb, SCAN_B>>>(n);
    k_fill<<<(E + 511) / 512, 512>>>(src, dst, E);

    // 3) node features
    k_features<<<(n * 32 + 255) / 256, 256>>>(nid, z, init_embed, z_table, n);

    // 4) 3 GCN layers (spmm: x->agg, gemm: agg->x)
    const int spmm_blocks = (n + 3) / 4;
    const int gemm_blocks = (n + 127) / 128;
    k_spmm<<<spmm_blocks, 128>>>(n);
    k_gemm<<<gemm_blocks, 256>>>(W0, b0, n, 1);
    k_spmm<<<spmm_blocks, 128>>>(n);
    k_gemm<<<gemm_blocks, 256>>>(W1, b1, n, 1);
    k_spmm<<<spmm_blocks, 128>>>(n);
    k_gemm<<<gemm_blocks, 256>>>(W2, b2, n, 0);

    // 5) fused pooling + MLP head
    k_pool_mlp<<<G_CNT, 256>>>(graph_id, n, lin1_W, lin1_b, lin2_W, lin2_b, out);
}

// round 3
// speedup vs baseline: 1.2045x; 1.0654x over previous
#include <cuda_runtime.h>
#include <cuda_bf16.h>
#include <cstdint>

// Problem constants (shapes fixed by the dataset)
#define N_MAX   50000
#define E_MAX   800000
#define G_CNT   512
#define FDIM    128
#define OUTD    200
#define SCAN_B  1024

// ---------------- device scratch (static, no allocation) ----------------
__device__ __align__(128) float g_x[N_MAX * FDIM];     // node features (ping), pre-scaled by norm_out when feeding an SpMM
__device__ __align__(128) float g_agg[N_MAX * FDIM];   // aggregated (pong)
__device__ int   g_deg[2 * N_MAX];                     // [0..N) = deg_out, [N..2N) = deg_in
__device__ float g_norm_out[N_MAX];
__device__ float g_norm_in[N_MAX];
__device__ int   g_row_off[N_MAX + 1];
__device__ int   g_cursor[N_MAX];
__device__ int   g_esrc[E_MAX];                        // edge sources grouped by dst
__device__ int   g_bsum[64];                           // block sums for the scan

// ---------------- kernels ----------------

__global__ void k_zero_deg(int n2) {
    for (int i = blockIdx.x * blockDim.x + threadIdx.x; i < n2; i += gridDim.x * blockDim.x)
        g_deg[i] = 0;
}

__global__ void k_deg(const int* __restrict__ src, const int* __restrict__ dst, int E, int n) {
    for (int e = blockIdx.x * blockDim.x + threadIdx.x; e < E; e += gridDim.x * blockDim.x) {
        atomicAdd(&g_deg[src[e]], 1);          // deg_out
        atomicAdd(&g_deg[n + dst[e]], 1);      // deg_in
    }
}

// Phase 1: per-block inclusive scan of deg_in -> g_row_off[i+1] (block-local),
// block total -> g_bsum. Also fuses norm computation and cursor zeroing.
__global__ void __launch_bounds__(SCAN_B) k_scan1(int n) {
    __shared__ int wsum[32];
    const int tid = threadIdx.x, lane = tid & 31, wid = tid >> 5;
    const int i = blockIdx.x * SCAN_B + tid;
    int v = 0;
    if (i < n) {
        v = g_deg[n + i];                       // deg_in
        g_cursor[i] = 0;
        g_norm_out[i] = rsqrtf(fmaxf((float)g_deg[i], 1.0f));
        g_norm_in[i]  = rsqrtf(fmaxf((float)v, 1.0f));
    }
    int x = v;
    #pragma unroll
    for (int off = 1; off < 32; off <<= 1) {
        int t = __shfl_up_sync(0xffffffffu, x, off);
        if (lane >= off) x += t;
    }
    if (lane == 31) wsum[wid] = x;
    __syncthreads();
    if (wid == 0) {
        int w = wsum[lane];
        #pragma unroll
        for (int off = 1; off < 32; off <<= 1) {
            int t = __shfl_up_sync(0xffffffffu, w, off);
            if (lane >= off) w += t;
        }
        wsum[lane] = w;
    }
    __syncthreads();
    int incl = x + (wid > 0 ? wsum[wid - 1] : 0);
    if (i < n) g_row_off[i + 1] = incl;
    if (tid == SCAN_B - 1) g_bsum[blockIdx.x] = incl;   // block total
    if (i == 0) g_row_off[0] = 0;
}

// Phase 2: exclusive scan of <=64 block sums in a single warp.
__global__ void k_scan2(int nb) {
    const int lane = threadIdx.x;   // 32 threads
    int v0 = (lane < nb) ? g_bsum[lane] : 0;
    int v1 = (lane + 32 < nb) ? g_bsum[lane + 32] : 0;
    int x0 = v0, x1 = v1;
    #pragma unroll
    for (int off = 1; off < 32; off <<= 1) {
        int t0 = __shfl_up_sync(0xffffffffu, x0, off);
        int t1 = __shfl_up_sync(0xffffffffu, x1, off);
        if (lane >= off) { x0 += t0; x1 += t1; }
    }
    int tot0 = __shfl_sync(0xffffffffu, x0, 31);
    if (lane < nb) g_bsum[lane] = x0 - v0;
    if (lane + 32 < nb) g_bsum[lane + 32] = x1 - v1 + tot0;
}

// Phase 3: add block offsets.
__global__ void __launch_bounds__(SCAN_B) k_scan3(int n) {
    int i = blockIdx.x * SCAN_B + threadIdx.x;
    if (i < n) g_row_off[i + 1] += g_bsum[blockIdx.x];
}

__global__ void k_fill(const int* __restrict__ src, const int* __restrict__ dst, int E) {
    for (int e = blockIdx.x * blockDim.x + threadIdx.x; e < E; e += gridDim.x * blockDim.x) {
        int d = dst[e];
        int p = g_row_off[d] + atomicAdd(&g_cursor[d], 1);
        g_esrc[p] = src[e];
    }
}

// x = concat(init_embed[nid], z_table[z]) * norm_out[node]   (pre-scaled for SpMM)
__global__ void k_features(const int* __restrict__ nid, const int* __restrict__ z,
                           const float* __restrict__ init_embed,
                           const float* __restrict__ z_table, int n) {
    int total = n * 32;  // float4 units per node = 128/4
    for (int idx = blockIdx.x * blockDim.x + threadIdx.x; idx < total; idx += gridDim.x * blockDim.x) {
        int node = idx >> 5, q = idx & 31;
        float4 v;
        if (q < 16) v = __ldg(&((const float4*)init_embed)[(long)nid[node] * 16 + q]);
        else        v = __ldg(&((const float4*)z_table)[(long)z[node] * 16 + (q - 16)]);
        float s = g_norm_out[node];
        ((float4*)g_x)[node * 32 + q] = make_float4(v.x * s, v.y * s, v.z * s, v.w * s);
    }
}

// SpMM gather-reduce: warp per dst node; lane covers 4 floats (float4).
// g_x is pre-scaled by norm_out, so this is a pure add-gather.
// agg[d] = norm_in[d] * sum_{e in row(d)} x_scaled[src]
__global__ void __launch_bounds__(128) k_spmm(int n) {
    int warp = blockIdx.x * (blockDim.x >> 5) + (threadIdx.x >> 5);
    int lane = threadIdx.x & 31;
    if (warp >= n) return;
    int e0 = g_row_off[warp], e1 = g_row_off[warp + 1];
    float4 a0 = make_float4(0.f, 0.f, 0.f, 0.f);
    float4 a1 = a0, a2 = a0, a3 = a0;
    const float4* x4 = (const float4*)g_x;
    int e = e0;
    for (; e + 3 < e1; e += 4) {
        int s0 = __ldg(&g_esrc[e]);
        int s1 = __ldg(&g_esrc[e + 1]);
        int s2 = __ldg(&g_esrc[e + 2]);
        int s3 = __ldg(&g_esrc[e + 3]);
        float4 v0 = __ldg(&x4[s0 * 32 + lane]);
        float4 v1 = __ldg(&x4[s1 * 32 + lane]);
        float4 v2 = __ldg(&x4[s2 * 32 + lane]);
        float4 v3 = __ldg(&x4[s3 * 32 + lane]);
        a0.x += v0.x; a0.y += v0.y; a0.z += v0.z; a0.w += v0.w;
        a1.x += v1.x; a1.y += v1.y; a1.z += v1.z; a1.w += v1.w;
        a2.x += v2.x; a2.y += v2.y; a2.z += v2.z; a2.w += v2.w;
        a3.x += v3.x; a3.y += v3.y; a3.z += v3.z; a3.w += v3.w;
    }
    for (; e < e1; e++) {
        int s0 = __ldg(&g_esrc[e]);
        float4 v0 = __ldg(&x4[s0 * 32 + lane]);
        a0.x += v0.x; a0.y += v0.y; a0.z += v0.z; a0.w += v0.w;
    }
    float ni = g_norm_in[warp];
    ((float4*)g_agg)[warp * 32 + lane] =
        make_float4((a0.x + a1.x + a2.x + a3.x) * ni,
                    (a0.y + a1.y + a2.y + a3.y) * ni,
                    (a0.z + a1.z + a2.z + a3.z) * ni,
                    (a0.w + a1.w + a2.w + a3.w) * ni);
}

// Packed-FMA SGEMM using fma.rn.f32x2 (2 fp32 FMAs per instruction).
// out[n,128] = act(g_agg[n,128] @ W[128,128] + b) [* norm_out[row]]
// Smem holds (k_even, k_odd) float2 pairs so both operands load pre-packed.
// Thread (tm, tn) computes rows tm*8..+8, cols {tn + 16*j, j=0..7}.
__global__ void __launch_bounds__(256) k_gemm(const float* __restrict__ W,
                                              const float* __restrict__ bias,
                                              int n, int relu, int scaleOut) {
    __shared__ __align__(16) float2 As2[8][FDIM + 2];  // [k/2][m]
    __shared__ __align__(16) float2 Bs2[8][FDIM + 2];  // [k/2][col]
    const int tid = threadIdx.x;
    const int tn = tid & 15;
    const int tm = tid >> 4;
    const int row0 = blockIdx.x * 128;

    unsigned long long acc[8][8];
    #pragma unroll
    for (int i = 0; i < 8; i++)
        #pragma unroll
        for (int j = 0; j < 8; j++) acc[i][j] = 0ull;

    // bias for this thread's 8 columns (stride 16)
    float bb[8];
    #pragma unroll
    for (int j = 0; j < 8; j++) bb[j] = __ldg(&bias[tn + 16 * j]);

    const float4* A4 = (const float4*)g_agg;

    for (int k0 = 0; k0 < FDIM; k0 += 16) {
        // A chunk: 128 rows x 16 k -> paired-k layout
        #pragma unroll
        for (int l = 0; l < 2; l++) {
            int fid = tid + l * 256;
            int r = fid >> 2;          // row within tile
            int kq = fid & 3;          // which float4 of the 16-k chunk
            int grow = row0 + r;
            float4 v = make_float4(0.f, 0.f, 0.f, 0.f);
            if (grow < n) v = A4[grow * 32 + (k0 >> 2) + kq];
            As2[kq * 2 + 0][r] = make_float2(v.x, v.y);
            As2[kq * 2 + 1][r] = make_float2(v.z, v.w);
        }
        // W chunk: 16 rows x 128 cols -> paired-k layout (scalar, coalesced)
        {
            int col = tid & 127;
            int kk2base = (tid >> 7) * 4;
            #pragma unroll
            for (int q = 0; q < 4; q++) {
                int kk2 = kk2base + q;
                float e = __ldg(&W[(k0 + 2 * kk2)     * FDIM + col]);
                float o = __ldg(&W[(k0 + 2 * kk2 + 1) * FDIM + col]);
                Bs2[kk2][col] = make_float2(e, o);
            }
        }
        __syncthreads();
        #pragma unroll
        for (int kk2 = 0; kk2 < 8; kk2++) {
            // a: 8 packed pairs, contiguous -> 4x LDS.128
            const ulonglong2* ap = (const ulonglong2*)&As2[kk2][tm * 8];
            ulonglong2 p0 = ap[0], p1 = ap[1], p2 = ap[2], p3 = ap[3];
            unsigned long long av[8] = {p0.x, p0.y, p1.x, p1.y, p2.x, p2.y, p3.x, p3.y};
            // b: 8 packed pairs, stride-16 cols -> scalar LDS.64, conflict-free
            unsigned long long bv[8];
            #pragma unroll
            for (int j = 0; j < 8; j++)
                bv[j] = *(const unsigned long long*)&Bs2[kk2][tn + 16 * j];
            #pragma unroll
            for (int i = 0; i < 8; i++)
                #pragma unroll
                for (int j = 0; j < 8; j++)
                    asm("fma.rn.f32x2 %0, %1, %2, %0;"
                        : "+l"(acc[i][j]) : "l"(av[i]), "l"(bv[j]));
        }
        __syncthreads();
    }

    // epilogue: combine halves, bias, relu, optional norm_out scaling
    #pragma unroll
    for (int i = 0; i < 8; i++) {
        int grow = row0 + tm * 8 + i;
        if (grow >= n) break;
        float s = scaleOut ? g_norm_out[grow] : 1.0f;
        #pragma unroll
        for (int j = 0; j < 8; j++) {
            float2 p = *(float2*)&acc[i][j];
            float v = p.x + p.y + bb[j];
            if (relu) v = fmaxf(v, 0.f);
            g_x[grow * FDIM + tn + 16 * j] = v * s;
        }
    }
}

// Fused pooling + MLP head. graph_id is sorted -> contiguous node ranges.
__global__ void __launch_bounds__(256) k_pool_mlp(const int* __restrict__ gid, int n,
                                                  const float* __restrict__ lin1_W,
                                                  const float* __restrict__ lin1_b,
                                                  const float* __restrict__ lin2_W,
                                                  const float* __restrict__ lin2_b,
                                                  float* __restrict__ out) {
    __shared__ float gs[FDIM];
    __shared__ float hs[FDIM];
    __shared__ int s_lo, s_hi;
    const int g = blockIdx.x;
    const int tid = threadIdx.x;

    if (tid == 0) {
        int lo = 0, hi = n;
        while (lo < hi) { int m = (lo + hi) >> 1; if (__ldg(&gid[m]) < g) lo = m + 1; else hi = m; }
        s_lo = lo;
    } else if (tid == 32) {
        int lo = 0, hi = n;
        while (lo < hi) { int m = (lo + hi) >> 1; if (__ldg(&gid[m]) <= g) lo = m + 1; else hi = m; }
        s_hi = lo;
    }
    __syncthreads();

    const int lo = s_lo, hi = s_hi;
    if (tid < FDIM) {
        float acc = 0.f;
        for (int node = lo; node < hi; node++)
            acc += g_x[node * FDIM + tid];
        gs[tid] = acc;
    }
    __syncthreads();
    if (tid < FDIM) {
        float acc = __ldg(&lin1_b[tid]);
        #pragma unroll 8
        for (int k = 0; k < FDIM; k++)
            acc += gs[k] * __ldg(&lin1_W[k * FDIM + tid]);
        hs[tid] = fmaxf(acc, 0.f);
    }
    __syncthreads();
    for (int c = tid; c < OUTD; c += blockDim.x) {
        float acc = __ldg(&lin2_b[c]);
        #pragma unroll 8
        for (int k = 0; k < FDIM; k++)
            acc += hs[k] * __ldg(&lin2_W[k * OUTD + c]);
        out[g * OUTD + c] = acc;
    }
}

// ---------------- launch ----------------
extern "C" void kernel_launch(void* const* d_in, const int* in_sizes, int n_in,
                              void* d_out, int out_size) {
    const int*   nid        = (const int*)  d_in[0];
    const int*   z          = (const int*)  d_in[1];
    const int*   src        = (const int*)  d_in[2];
    const int*   dst        = (const int*)  d_in[3];
    const int*   graph_id   = (const int*)  d_in[4];
    const float* init_embed = (const float*)d_in[5];
    const float* z_table    = (const float*)d_in[6];
    const float* W0 = (const float*)d_in[7];
    const float* b0 = (const float*)d_in[8];
    const float* W1 = (const float*)d_in[9];
    const float* b1 = (const float*)d_in[10];
    const float* W2 = (const float*)d_in[11];
    const float* b2 = (const float*)d_in[12];
    const float* lin1_W = (const float*)d_in[13];
    const float* lin1_b = (const float*)d_in[14];
    const float* lin2_W = (const float*)d_in[15];
    const float* lin2_b = (const float*)d_in[16];
    float* out = (float*)d_out;

    const int n = in_sizes[0];       // 50000
    const int E = in_sizes[2];       // 800000
    const int nb = (n + SCAN_B - 1) / SCAN_B;

    // 1) degrees
    k_zero_deg<<<256, 256>>>(2 * n);
    k_deg<<<(E + 511) / 512, 512>>>(src, dst, E, n);

    // 2) norms + CSR row offsets (3-phase scan), then fill
    k_scan1<<<nb, SCAN_B>>>(n);
    k_scan2<<<1, 32>>>(nb);
    k_scan3<<<nb, SCAN_B>>>(n);
    k_fill<<<(E + 511) / 512, 512>>>(src, dst, E);

    // 3) node features (pre-scaled by norm_out; needs k_scan1's norms)
    k_features<<<(n * 32 + 255) / 256, 256>>>(nid, z, init_embed, z_table, n);

    // 4) 3 GCN layers (spmm: x->agg, gemm: agg->x)
    const int spmm_blocks = (n + 3) / 4;
    const int gemm_blocks = (n + 127) / 128;
    k_spmm<<<spmm_blocks, 128>>>(n);
    k_gemm<<<gemm_blocks, 256>>>(W0, b0, n, 1, 1);
    k_spmm<<<spmm_blocks, 128>>>(n);
    k_gemm<<<gemm_blocks, 256>>>(W1, b1, n, 1, 1);
    k_spmm<<<spmm_blocks, 128>>>(n);
    k_gemm<<<gemm_blocks, 256>>>(W2, b2, n, 0, 0);

    // 5) fused pooling + MLP head
    k_pool_mlp<<<G_CNT, 256>>>(graph_id, n, lin1_W, lin1_b, lin2_W, lin2_b, out);
}